// round 17
// baseline (speedup 1.0000x reference)
#include <cuda_runtime.h>
#include <cuda_fp16.h>
#include <math.h>

// ---------------------------------------------------------------------------
// PortfolioGAT: 2-layer GAT, N=100000, 1.6M edges + self loops.
// Round 15: order-free CSR offsets (1 kernel, atomic block bases) replaces the
// 3-kernel scan; zero/cleanup folded into k_agg2 (self-restoring state);
// agg1 computes edge exps once per edge (lane-parallel) and stages
// {src,w0,w1} in smem — MUFU pressure /16. 6 kernels total, CSR || GEMM.
// ---------------------------------------------------------------------------

#define MAXN 100000
#define MAXE 1600000
#define C1 32
#define NEG_SLOPE 0.2f

// ---- scratch (zero-initialized at module load; every call restores zeros) ----
__device__ int    g_deg[MAXN];        // histogram (len per dst); zeroed by k_agg2
__device__ int    g_row[MAXN];        // region start per dst
__device__ int    g_cur[MAXN];        // scatter cursor
__device__ int    g_pos;              // global region cursor; zeroed by k_agg2
__device__ int    g_srt[MAXE];        // src ids grouped by dst
__device__ __half g_h1h[MAXN * C1];   // x @ W1, fp16
__device__ float  g_as1[MAXN * 2];
__device__ float  g_ad1[MAXN * 2];
__device__ float2 g_sh2[MAXN];        // {as2, h2}
__device__ float  g_ad2[MAXN];

__device__ __forceinline__ float lrelu(float v) { return v > 0.f ? v : NEG_SLOPE * v; }

// ---- CSR build ---------------------------------------------------------------
__global__ void k_hist(const int* __restrict__ ei, int E) {
    int i = (blockIdx.x * blockDim.x + threadIdx.x) * 2;
    if (i + 1 < E) {
        int2 d = *(const int2*)&ei[E + i];
        atomicAdd(&g_deg[d.x], 1);
        atomicAdd(&g_deg[d.y], 1);
    } else if (i < E) {
        atomicAdd(&g_deg[ei[E + i]], 1);
    }
}

// one kernel: block-local exclusive scan of degrees + one atomicAdd per block
// for the block's base. Regions are disjoint+contiguous; order irrelevant.
__global__ __launch_bounds__(256)
void k_offsets(int N) {
    __shared__ int sWarp[32];
    __shared__ int sBase;
    int i = blockIdx.x * blockDim.x + threadIdx.x;
    int lane = threadIdx.x & 31, wid = threadIdx.x >> 5;
    int v = (i < N) ? g_deg[i] : 0;

    int x = v;
    #pragma unroll
    for (int off = 1; off < 32; off <<= 1) {
        int y = __shfl_up_sync(0xffffffffu, x, off);
        if (lane >= off) x += y;
    }
    if (lane == 31) sWarp[wid] = x;
    __syncthreads();
    if (wid == 0) {
        int t = (lane < 8) ? sWarp[lane] : 0;
        #pragma unroll
        for (int off = 1; off < 8; off <<= 1) {
            int y = __shfl_up_sync(0xffffffffu, t, off);
            if (lane >= off) t += y;
        }
        sWarp[lane] = t;
        if (lane == 7) sBase = atomicAdd(&g_pos, t);   // block total -> base
    }
    __syncthreads();
    int incl = x + (wid > 0 ? sWarp[wid - 1] : 0);
    if (i < N) {
        int st = sBase + incl - v;
        g_row[i] = st;
        g_cur[i] = st;
    }
}

__global__ void k_scatter(const int* __restrict__ ei, int E) {
    int i = (blockIdx.x * blockDim.x + threadIdx.x) * 2;
    if (i + 1 < E) {
        int2 s = *(const int2*)&ei[i];
        int2 d = *(const int2*)&ei[E + i];
        g_srt[atomicAdd(&g_cur[d.x], 1)] = s.x;
        g_srt[atomicAdd(&g_cur[d.y], 1)] = s.y;
    } else if (i < E) {
        g_srt[atomicAdd(&g_cur[ei[E + i]], 1)] = ei[i];
    }
}

// ---- GEMM: h1 = x @ W1 (fp16 out), plus per-node attention projections --------
__global__ __launch_bounds__(256)
void k_gemm(const float* __restrict__ x, const float* __restrict__ W1,
            const float* __restrict__ a_s, const float* __restrict__ a_d, int N) {
    __shared__ float sW[128 * 32];
    __shared__ float sx[64 * 68];

    int tid = threadIdx.x;
    for (int i = tid; i < 128 * 32; i += 256) sW[i] = W1[i];

    int base = blockIdx.x * 64;
    int col4 = (tid & 7) * 4;
    int n0   = (tid >> 3) * 2;

    float acc[2][4] = {{0.f,0.f,0.f,0.f},{0.f,0.f,0.f,0.f}};

    for (int kc = 0; kc < 128; kc += 64) {
        __syncthreads();
        #pragma unroll
        for (int it = 0; it < 4; ++it) {
            int slot = tid + it * 256;
            int row  = slot >> 4;
            int cq   = slot & 15;
            int gn   = base + row;
            float4 v = make_float4(0.f, 0.f, 0.f, 0.f);
            if (gn < N) v = *(const float4*)&x[gn * 128 + kc + cq * 4];
            *(float4*)&sx[row * 68 + cq * 4] = v;
        }
        __syncthreads();

        #pragma unroll 16
        for (int k = 0; k < 64; ++k) {
            float4 w = *(const float4*)&sW[(kc + k) * 32 + col4];
            float x0 = sx[n0 * 68 + k];
            float x1 = sx[(n0 + 1) * 68 + k];
            acc[0][0] = fmaf(x0, w.x, acc[0][0]);
            acc[0][1] = fmaf(x0, w.y, acc[0][1]);
            acc[0][2] = fmaf(x0, w.z, acc[0][2]);
            acc[0][3] = fmaf(x0, w.w, acc[0][3]);
            acc[1][0] = fmaf(x1, w.x, acc[1][0]);
            acc[1][1] = fmaf(x1, w.y, acc[1][1]);
            acc[1][2] = fmaf(x1, w.z, acc[1][2]);
            acc[1][3] = fmaf(x1, w.w, acc[1][3]);
        }
    }

    int head = col4 >> 4;
    int cc   = col4 & 15;
    float as4[4], ad4[4];
    #pragma unroll
    for (int c = 0; c < 4; ++c) {
        as4[c] = a_s[head * 16 + cc + c];
        ad4[c] = a_d[head * 16 + cc + c];
    }
    #pragma unroll
    for (int j = 0; j < 2; ++j) {
        int n = base + n0 + j;
        float va = acc[j][0]*as4[0] + acc[j][1]*as4[1] + acc[j][2]*as4[2] + acc[j][3]*as4[3];
        float vd = acc[j][0]*ad4[0] + acc[j][1]*ad4[1] + acc[j][2]*ad4[2] + acc[j][3]*ad4[3];
        va += __shfl_xor_sync(0xffffffffu, va, 1);
        va += __shfl_xor_sync(0xffffffffu, va, 2);
        vd += __shfl_xor_sync(0xffffffffu, vd, 1);
        vd += __shfl_xor_sync(0xffffffffu, vd, 2);
        if (n < N) {
            __half2 p0 = __floats2half2_rn(acc[j][0], acc[j][1]);
            __half2 p1 = __floats2half2_rn(acc[j][2], acc[j][3]);
            __half2* hp = (__half2*)&g_h1h[n * C1 + col4];
            hp[0] = p0; hp[1] = p1;
            if ((tid & 3) == 0) {
                g_as1[n * 2 + head] = va;
                g_ad1[n * 2 + head] = vd;
            }
        }
    }
}

// ---- layer-1 aggregate + normalize + ELU + layer-2 projection, fused ---------
// One warp per dst node; lane = channel. Edge weights computed ONCE per edge
// (lane-parallel), staged in smem {src, w_head0, w_head1}, broadcast-read.
__global__ __launch_bounds__(256)
void k_agg1(const float* __restrict__ b1, const float* __restrict__ W2,
            const float* __restrict__ As2, const float* __restrict__ Ad2, int N) {
    __shared__ float4 stage[8][32];
    int warp = (blockIdx.x * blockDim.x + threadIdx.x) >> 5;
    int lane = threadIdx.x & 31;
    int wib  = (threadIdx.x >> 5);
    if (warp >= N) return;
    int d = warp;
    bool h0 = lane < 16;

    float2 adp = *(const float2*)&g_ad1[2 * d];
    float2 asp = *(const float2*)&g_as1[2 * d];
    float ad_h = h0 ? adp.x : adp.y;

    // self loop
    float w = __expf(lrelu((h0 ? asp.x : asp.y) + ad_h));
    float den = w;
    float acc = w * __half2float(g_h1h[d * C1 + lane]);

    int start = g_row[d], len = g_deg[d];
    for (int base = 0; base < len; base += 32) {
        int m = len - base; if (m > 32) m = 32;
        // stage phase: lane handles edge (base+lane)
        float4 st = make_float4(0.f, 0.f, 0.f, 0.f);
        if (lane < m) {
            int sb = g_srt[start + base + lane];
            float2 a = __ldg(&((const float2*)g_as1)[sb]);
            st.x = __int_as_float(sb);
            st.y = __expf(lrelu(a.x + adp.x));
            st.z = __expf(lrelu(a.y + adp.y));
        }
        __syncwarp();
        stage[wib][lane] = st;
        __syncwarp();

        int k = 0;
        for (; k + 4 <= m; k += 4) {
            float4 e0 = stage[wib][k];
            float4 e1 = stage[wib][k + 1];
            float4 e2 = stage[wib][k + 2];
            float4 e3 = stage[wib][k + 3];
            int s0 = __float_as_int(e0.x), s1 = __float_as_int(e1.x);
            int s2 = __float_as_int(e2.x), s3 = __float_as_int(e3.x);
            float f0 = __half2float(g_h1h[s0 * C1 + lane]);
            float f1 = __half2float(g_h1h[s1 * C1 + lane]);
            float f2 = __half2float(g_h1h[s2 * C1 + lane]);
            float f3 = __half2float(g_h1h[s3 * C1 + lane]);
            float w0 = h0 ? e0.y : e0.z;
            float w1 = h0 ? e1.y : e1.z;
            float w2 = h0 ? e2.y : e2.z;
            float w3 = h0 ? e3.y : e3.z;
            acc = fmaf(w0, f0, acc); den += w0;
            acc = fmaf(w1, f1, acc); den += w1;
            acc = fmaf(w2, f2, acc); den += w2;
            acc = fmaf(w3, f3, acc); den += w3;
        }
        for (; k < m; ++k) {
            float4 e = stage[wib][k];
            int s = __float_as_int(e.x);
            float f = __half2float(g_h1h[s * C1 + lane]);
            float ww = h0 ? e.y : e.z;
            acc = fmaf(ww, f, acc); den += ww;
        }
    }

    float o = acc / den + b1[lane];
    o = o > 0.f ? o : (__expf(o) - 1.f);
    float c = o * W2[lane];
    #pragma unroll
    for (int off = 16; off; off >>= 1)
        c += __shfl_xor_sync(0xffffffffu, c, off);
    if (lane == 0) {
        g_sh2[d] = make_float2(c * As2[0], c);
        g_ad2[d] = c * Ad2[0];
    }
}

// ---- layer-2 + state cleanup (restores zero invariants for next call) --------
__global__ __launch_bounds__(256)
void k_agg2(float* __restrict__ out, const float* __restrict__ b2, int N) {
    int warp = (blockIdx.x * blockDim.x + threadIdx.x) >> 5;
    int lane = threadIdx.x & 31;
    if (warp >= N) return;
    int d = warp;
    float ad = g_ad2[d];
    float num = 0.f, den = 0.f;
    int start = g_row[d], len = g_deg[d];
    for (int k = lane; k < len; k += 32) {
        int s = g_srt[start + k];
        float2 p = __ldg(&((const float2*)g_sh2)[s]);
        float w = __expf(lrelu(p.x + ad));
        num = fmaf(w, p.y, num); den += w;
    }
    if (lane == 0) {
        float2 p = g_sh2[d];
        float w = __expf(lrelu(p.x + ad));
        num = fmaf(w, p.y, num); den += w;
    }
    #pragma unroll
    for (int off = 16; off; off >>= 1) {
        num += __shfl_xor_sync(0xffffffffu, num, off);
        den += __shfl_xor_sync(0xffffffffu, den, off);
    }
    if (lane == 0) {
        out[d] = num / den + b2[0];
        g_deg[d] = 0;                         // restore zero for next call
        if (d == 0) g_pos = 0;
    }
}

// ---- launch --------------------------------------------------------------------
extern "C" void kernel_launch(void* const* d_in, const int* in_sizes, int n_in,
                              void* d_out, int out_size) {
    const float* x     = (const float*)d_in[0];
    const int*   ei    = (const int*)  d_in[1];
    const float* W1    = (const float*)d_in[2];
    const float* a_s1  = (const float*)d_in[3];
    const float* a_d1  = (const float*)d_in[4];
    const float* b1    = (const float*)d_in[5];
    const float* W2    = (const float*)d_in[6];
    const float* a_s2  = (const float*)d_in[7];
    const float* a_d2  = (const float*)d_in[8];
    const float* b2    = (const float*)d_in[9];
    float*       out   = (float*)d_out;

    int N  = in_sizes[0] / 128;
    int E  = in_sizes[1] / 2;
    if (N > MAXN || E > MAXE) return;

    const int T = 256;
    auto blks = [T](long long n) { return (int)((n + T - 1) / T); };

    // fork: CSR build (hist -> offsets -> scatter) runs concurrently with GEMM
    cudaStream_t s2;
    cudaStreamCreateWithFlags(&s2, cudaStreamNonBlocking);
    cudaEvent_t evFork, evJoin;
    cudaEventCreateWithFlags(&evFork, cudaEventDisableTiming);
    cudaEventCreateWithFlags(&evJoin, cudaEventDisableTiming);

    cudaEventRecord(evFork, 0);
    cudaStreamWaitEvent(s2, evFork, 0);

    k_hist   <<<blks((E + 1) / 2), T, 0, s2>>>(ei, E);
    k_offsets<<<blks(N), T, 0, s2>>>(N);
    k_scatter<<<blks((E + 1) / 2), T, 0, s2>>>(ei, E);
    cudaEventRecord(evJoin, s2);

    k_gemm<<<(N + 63) / 64, T>>>(x, W1, a_s1, a_d1, N);

    cudaStreamWaitEvent(0, evJoin, 0);
    k_agg1<<<blks((long long)N * 32), T>>>(b1, W2, a_s2, a_d2, N);
    k_agg2<<<blks((long long)N * 32), T>>>(out, b2, N);
}